// round 11
// baseline (speedup 1.0000x reference)
#include <cuda_runtime.h>
#include <math.h>
#include <stdint.h>

#define N_PTS 65536
#define E_EXP 8
#define F_DIM 236
#define M_DIM 441
#define NLAYER 5

// ---- siren tiling ----
#define TMS   128           // points per CTA
#define SKS   30            // total ksteps (K padded 240)
#define SKC   5             // ksteps per B chunk
#define SNCH  6             // chunks per layer
#define SNPAD 260           // B n-pad (f2 row len)
#define SSLAB (SKC*4*SNPAD) // 5200 f2 per B slab (41600 B)
#define SABUF (SKS*TMS*4)   // 15360 f2, single in-place A buffer
#define SBYTES (SSLAB*8)

// ---- gate tiling ----
#define GM    128
#define GNT   112
#define GKC   4             // ksteps per chunk
#define GNCH  14            // K padded 448
#define GNPAD 116
#define GASLAB (GKC*GM*4)    // 2048 f2 (16384 B)
#define GBSLAB (GKC*4*GNPAD) // 1856 f2 (14848 B)
#define GBYTES (GASLAB*8 + GBSLAB*8)

// ---------------- helpers ----------------
__device__ __forceinline__ float tf32q(float x) {
    float r; asm("cvt.rna.tf32.f32 %0, %1;" : "=f"(r) : "f"(x)); return r;
}
__device__ __forceinline__ uint32_t smem_u32(const void* p) {
    uint32_t a;
    asm("{ .reg .u64 t; cvta.to.shared.u64 t, %1; cvt.u32.u64 %0, t; }" : "=r"(a) : "l"(p));
    return a;
}
#define MBAR_INIT(a, n)  asm volatile("mbarrier.init.shared.b64 [%0], %1;" :: "r"(a), "r"((uint32_t)(n)) : "memory")
#define MBAR_EXPECT_TX(a, n) asm volatile("mbarrier.arrive.expect_tx.shared.b64 _, [%0], %1;" :: "r"(a), "r"((uint32_t)(n)) : "memory")
#define MBAR_WAIT(a, ph) do {                                                   \
    uint32_t _m = (a); uint32_t _p = (ph); uint32_t _d;                         \
    asm volatile("{\n\t.reg .pred p;\n\t"                                       \
        "mbarrier.try_wait.parity.acquire.cta.shared::cta.b64 p, [%1], %2;\n\t" \
        "selp.b32 %0, 1, 0, p;\n\t}" : "=r"(_d) : "r"(_m), "r"(_p) : "memory"); \
    if (!_d) {                                                                  \
        asm volatile("{\n\t.reg .pred P1;\n\t"                                  \
            "W%=:\n\t"                                                          \
            "mbarrier.try_wait.parity.acquire.cta.shared::cta.b64 P1, [%0], %1, 0x989680;\n\t" \
            "@P1 bra.uni D%=;\n\t"                                              \
            "bra.uni W%=;\n\t"                                                  \
            "D%=:\n\t}" :: "r"(_m), "r"(_p) : "memory");                        \
    } } while (0)
#define BULK_G2S(dst, src, bytes, mbar) \
    asm volatile("cp.async.bulk.shared::cluster.global.mbarrier::complete_tx::bytes [%0], [%1], %2, [%3];" \
        :: "r"(dst), "l"(src), "r"((uint32_t)(bytes)), "r"(mbar) : "memory")
#define REDADD(addr, v) \
    asm volatile("red.global.add.f32 [%0], %1;" :: "l"(addr), "f"(v) : "memory")

__device__ __forceinline__ void mma8(float* d, const uint32_t* a, uint32_t b0, uint32_t b1) {
    asm volatile(
        "mma.sync.aligned.m16n8k8.row.col.f32.tf32.tf32.f32 "
        "{%0,%1,%2,%3}, {%4,%5,%6,%7}, {%8,%9}, {%0,%1,%2,%3};"
        : "+f"(d[0]), "+f"(d[1]), "+f"(d[2]), "+f"(d[3])
        : "r"(a[0]), "r"(a[1]), "r"(a[2]), "r"(a[3]), "r"(b0), "r"(b1));
}
__device__ __forceinline__ uint32_t f2u(float f) { return __float_as_uint(f); }

// -------- device scratch --------
__device__ float g_logits[N_PTS * E_EXP];
__device__ int   g_expert[N_PTS];
__device__ int   g_counts[E_EXP];
__device__ int   g_offsets[E_EXP + 1];
__device__ int   g_cursor[E_EXP];
__device__ int   g_perm[N_PTS];
// g1 activations, A-fragment-paired: [band512][ch14][GASLAB f2]
__device__ __align__(16) float g_g1p[(size_t)512 * GNCH * GASLAB * 2];
// gate W2, bulk-ready: [tile4][ch14][GBSLAB f2]
__device__ __align__(16) float g_W2t[4 * GNCH * GBSLAB * 2];
// siren weights paired: [e][l][ch6][SSLAB f2]
__device__ __align__(16) float g_Bws[E_EXP * NLAYER * SNCH * SSLAB * 2];

// ---------------- init ----------------
__global__ void k_init() {
    int t = threadIdx.x;
    if (t < E_EXP) g_counts[t] = 0;
}

// ---------------- g1 precompute (paired A layout) + zero logits ----------------
__global__ void __launch_bounds__(256) k_g1(
    const float* __restrict__ x, const float* __restrict__ W1, const float* __restrict__ b1)
{
    __shared__ float xs[GM * 3];
    int band = blockIdx.x;
    for (int i = threadIdx.x; i < GM * 3; i += 256) xs[i] = tf32q(x[band * GM * 3 + i]);
    for (int i = threadIdx.x; i < GM * E_EXP; i += 256) g_logits[band * GM * E_EXP + i] = 0.f;
    __syncthreads();
    float2* dst = ((float2*)g_g1p) + (size_t)band * (GNCH * GASLAB);
    for (int s = threadIdx.x; s < 56 * GM * 4; s += 256) {
        int c = s & 3, r = (s >> 2) & 127, kt = s >> 9;    // kt 0..55
        int k0 = kt * 8 + c;
        const float* xr = xs + r * 3;
        float2 v; v.x = 0.f; v.y = 0.f;
        if (k0 < M_DIM)
            v.x = tf32q(fmaxf(xr[0] * tf32q(W1[k0]) + xr[1] * tf32q(W1[M_DIM + k0])
                            + xr[2] * tf32q(W1[2 * M_DIM + k0]) + b1[k0], 0.f));
        int k1 = k0 + 4;
        if (k1 < M_DIM)
            v.y = tf32q(fmaxf(xr[0] * tf32q(W1[k1]) + xr[1] * tf32q(W1[M_DIM + k1])
                            + xr[2] * tf32q(W1[2 * M_DIM + k1]) + b1[k1], 0.f));
        dst[s] = v;
    }
}

// ---------------- weight preps ----------------
__global__ void k_prep_gateB(const float* __restrict__ W2) {
    float2* dst = (float2*)g_W2t;
    const int total = 4 * GNCH * GBSLAB;
    for (int s = blockIdx.x * blockDim.x + threadIdx.x; s < total;
         s += gridDim.x * blockDim.x) {
        int n = s % GNPAD;
        int c = (s / GNPAD) & 3;
        int ks = (s / (GNPAD * 4)) & 3;
        int ch = (s / (GNPAD * 16)) % GNCH;
        int tile = s / (GNPAD * 16 * GNCH);
        int k0 = (ch * 4 + ks) * 8 + c;
        int col = tile * GNT + n;
        float2 v; v.x = 0.f; v.y = 0.f;
        if (n < GNT && col < M_DIM) {
            if (k0 < M_DIM)     v.x = tf32q(W2[(size_t)k0 * M_DIM + col]);
            if (k0 + 4 < M_DIM) v.y = tf32q(W2[(size_t)(k0 + 4) * M_DIM + col]);
        }
        dst[s] = v;
    }
}
__global__ void k_prep_siren(const float* __restrict__ sWh,
                             const float* __restrict__ sWo,
                             const float* __restrict__ dW1)
{
    int el = blockIdx.x >> 3;             // 0..39
    int part = blockIdx.x & 7;
    int e = el / NLAYER, l = el % NLAYER;
    const float* W;
    if (l < 3)       W = sWh + ((size_t)(l * E_EXP + e)) * F_DIM * F_DIM;
    else if (l == 3) W = sWo + (size_t)e * F_DIM * F_DIM;
    else             W = dW1 + (size_t)e * F_DIM * F_DIM;
    float2* dst = ((float2*)g_Bws) + (size_t)el * (SNCH * SSLAB);
    for (int s = part * 256 + threadIdx.x; s < SNCH * SSLAB; s += 2048) {
        int n = s % SNPAD, c = (s / SNPAD) & 3, ks = (s / (SNPAD * 4)) % 5, ch = s / SSLAB;
        int k0 = (ch * SKC + ks) * 8 + c;
        float2 v; v.x = 0.f; v.y = 0.f;
        if (n < F_DIM) {
            if (k0 < F_DIM)     v.x = tf32q(W[k0 * F_DIM + n]);
            if (k0 + 4 < F_DIM) v.y = tf32q(W[(k0 + 4) * F_DIM + n]);
        }
        dst[s] = v;
    }
}

// ---------------- gating GEMM + fused partial logits ----------------
__global__ void __launch_bounds__(256, 2) k_gate(
    const float* __restrict__ b2, const float* __restrict__ W3)
{
    extern __shared__ float smf[];
    float2* Af = (float2*)smf;                 // 2 x GASLAB
    float2* Bf = ((float2*)smf) + 2 * GASLAB;  // 2 x GBSLAB
    __shared__ __align__(8) unsigned long long mbar[2];
    const int tid = threadIdx.x;
    const int wid = tid >> 5, lane = tid & 31;
    const int r4 = lane >> 2, c4 = lane & 3;
    const int band = blockIdx.y;
    const int tile = blockIdx.x;
    const int wrow = (wid & 3) * 32;
    const int wcol = (wid >> 2) * 56;
    const uint32_t mb0 = smem_u32(&mbar[0]);

    const char* srcA = (const char*)g_g1p + (size_t)band * GNCH * (GASLAB * 8);
    const char* srcB = (const char*)g_W2t + (size_t)tile * GNCH * (GBSLAB * 8);

    float acc[2][7][4];
#pragma unroll
    for (int m = 0; m < 2; m++)
#pragma unroll
        for (int nb = 0; nb < 7; nb++)
#pragma unroll
            for (int j = 0; j < 4; j++) acc[m][nb][j] = 0.f;

    if (tid == 0) { MBAR_INIT(mb0, 1); MBAR_INIT(mb0 + 8, 1); }
    __syncthreads();
    if (tid == 0) {
        MBAR_EXPECT_TX(mb0, GBYTES);
        BULK_G2S(smem_u32(Af), srcA, GASLAB * 8, mb0);
        BULK_G2S(smem_u32(Bf), srcB, GBSLAB * 8, mb0);
    }

#pragma unroll 1
    for (int ch = 0; ch < GNCH; ch++) {
        const int s = ch & 1, ph = (ch >> 1) & 1;
        MBAR_WAIT(mb0 + 8 * s, ph);
        __syncthreads();
        if (ch + 1 < GNCH && tid == 0) {
            const int t = s ^ 1;
            MBAR_EXPECT_TX(mb0 + 8 * t, GBYTES);
            BULK_G2S(smem_u32(Af + t * GASLAB), srcA + (size_t)(ch + 1) * GASLAB * 8, GASLAB * 8, mb0 + 8 * t);
            BULK_G2S(smem_u32(Bf + t * GBSLAB), srcB + (size_t)(ch + 1) * GBSLAB * 8, GBSLAB * 8, mb0 + 8 * t);
        }
        const float2* Ab = Af + s * GASLAB;
        const float2* Bb = Bf + s * GBSLAB;
#pragma unroll
        for (int ks = 0; ks < GKC; ks++) {
            uint32_t a[2][4];
#pragma unroll
            for (int mb = 0; mb < 2; mb++) {
                int r = wrow + 16 * mb + r4;
                float2 p = Ab[(ks * GM + r) * 4 + c4];
                float2 q = Ab[(ks * GM + r + 8) * 4 + c4];
                a[mb][0] = f2u(p.x); a[mb][1] = f2u(q.x);
                a[mb][2] = f2u(p.y); a[mb][3] = f2u(q.y);
            }
#pragma unroll
            for (int nb = 0; nb < 7; nb++) {
                float2 b = Bb[(ks * 4 + c4) * GNPAD + wcol + nb * 8 + r4];
                mma8(acc[0][nb], a[0], f2u(b.x), f2u(b.y));
                mma8(acc[1][nb], a[1], f2u(b.x), f2u(b.y));
            }
        }
    }

    // fused epilogue: g2 = tf32q(relu(acc+b2)); partial logits = g2 . W3
    float s[4][8];
#pragma unroll
    for (int ri = 0; ri < 4; ri++)
#pragma unroll
        for (int ee = 0; ee < 8; ee++) s[ri][ee] = 0.f;
#pragma unroll
    for (int mb = 0; mb < 2; mb++) {
#pragma unroll
        for (int nb = 0; nb < 7; nb++) {
#pragma unroll
            for (int h = 0; h < 2; h++) {
                int col = tile * GNT + wcol + nb * 8 + 2 * c4 + h;
                if (col < M_DIM) {
                    float4 wa = *(const float4*)(W3 + col * 8);
                    float4 wb = *(const float4*)(W3 + col * 8 + 4);
                    float bb = b2[col];
#pragma unroll
                    for (int hr = 0; hr < 2; hr++) {
                        int ri = mb * 2 + hr;
                        float g = tf32q(fmaxf(acc[mb][nb][2 * hr + h] + bb, 0.f));
                        s[ri][0] = fmaf(g, tf32q(wa.x), s[ri][0]);
                        s[ri][1] = fmaf(g, tf32q(wa.y), s[ri][1]);
                        s[ri][2] = fmaf(g, tf32q(wa.z), s[ri][2]);
                        s[ri][3] = fmaf(g, tf32q(wa.w), s[ri][3]);
                        s[ri][4] = fmaf(g, tf32q(wb.x), s[ri][4]);
                        s[ri][5] = fmaf(g, tf32q(wb.y), s[ri][5]);
                        s[ri][6] = fmaf(g, tf32q(wb.z), s[ri][6]);
                        s[ri][7] = fmaf(g, tf32q(wb.w), s[ri][7]);
                    }
                }
            }
        }
    }
#pragma unroll
    for (int ri = 0; ri < 4; ri++)
#pragma unroll
        for (int ee = 0; ee < 8; ee++) {
            float v = s[ri][ee];
            v += __shfl_xor_sync(0xffffffffu, v, 1);
            v += __shfl_xor_sync(0xffffffffu, v, 2);
            s[ri][ee] = v;
        }
    if (c4 == 0) {
#pragma unroll
        for (int ri = 0; ri < 4; ri++) {
            int row = band * GM + wrow + 16 * (ri >> 1) + r4 + 8 * (ri & 1);
            float* dst = g_logits + (size_t)row * 8;
#pragma unroll
            for (int ee = 0; ee < 8; ee++) REDADD(dst + ee, s[ri][ee]);
        }
    }
}

// ---------------- argmax over fused logits ----------------
__global__ void __launch_bounds__(256) k_argmax(const float* __restrict__ b3) {
    int n = blockIdx.x * blockDim.x + threadIdx.x;
    if (n >= N_PTS) return;
    const float* lg = g_logits + (size_t)n * 8;
    float best = lg[0] + b3[0]; int bi = 0;
#pragma unroll
    for (int e = 1; e < 8; e++) {
        float v = lg[e] + b3[e];
        if (v > best) { best = v; bi = e; }
    }
    g_expert[n] = bi;
    atomicAdd(&g_counts[bi], 1);
}

// ---------------- scan + KL (one-hot => constant) ----------------
__global__ void k_scan(float* out, int kl_idx) {
    if (threadIdx.x == 0) {
        int off = 0;
        for (int e = 0; e < E_EXP; e++) {
            g_offsets[e] = off;
            off += g_counts[e];
            g_cursor[e] = 0;
        }
        g_offsets[E_EXP] = off;
        out[kl_idx] = logf(0.125f) - 0.875f * logf(1e-10f);
    }
}

// ---------------- scatter ----------------
__global__ void k_scatter() {
    int n = blockIdx.x * blockDim.x + threadIdx.x;
    if (n >= N_PTS) return;
    int e = g_expert[n];
    int p = atomicAdd(&g_cursor[e], 1);
    g_perm[g_offsets[e] + p] = n;
}

// ---------------- fused SIREN + decoder (tf32 mma, in-place A) ----------------
// TMS=128 points per CTA. Single A buffer: each warp owns rows [wrow,wrow+32)
// exclusively (reads its A frags, writes its epilogue) -> in-place is safe.
__global__ void __launch_bounds__(256, 1) k_siren(
    const float* __restrict__ x,
    const float* __restrict__ sW1, const float* __restrict__ sb1,
    const float* __restrict__ sbh, const float* __restrict__ sbo,
    const float* __restrict__ db1,
    const float* __restrict__ dW2, const float* __restrict__ db2,
    float* __restrict__ out)
{
    extern __shared__ float smf[];
    float2* Af2 = (float2*)smf;              // SABUF (in-place)
    float2* Bf2 = Af2 + SABUF;               // 2 x SSLAB
    __shared__ float xs[TMS * 3];
    __shared__ float part[2][TMS][3];
    __shared__ __align__(8) unsigned long long mbar[2];

    const int e = blockIdx.y;
    const int tid = threadIdx.x;
    const int wid = tid >> 5, lane = tid & 31;
    const int r4 = lane >> 2, c4 = lane & 3;
    const int beg = g_offsets[e], end = g_offsets[e + 1];
    const int start = beg + blockIdx.x * TMS;
    if (start >= end) return;
    const int npts = min(TMS, end - start);
    const uint32_t mb0 = smem_u32(&mbar[0]);

    const int wrow = (wid & 3) * 32;
    const int ng = wid >> 2;
    const int wcol = ng * 120;
    const char* bsrc = (const char*)g_Bws + (size_t)e * (NLAYER * SNCH) * SBYTES;

    if (tid == 0) { MBAR_INIT(mb0, 1); MBAR_INIT(mb0 + 8, 1); }
    if (tid < TMS) {
        float x0 = 0.f, x1 = 0.f, x2 = 0.f;
        if (tid < npts) {
            int n = g_perm[start + tid];
            x0 = tf32q(x[n * 3]); x1 = tf32q(x[n * 3 + 1]); x2 = tf32q(x[n * 3 + 2]);
        }
        xs[tid * 3] = x0; xs[tid * 3 + 1] = x1; xs[tid * 3 + 2] = x2;
    }
    __syncthreads();
    if (tid == 0) {
        MBAR_EXPECT_TX(mb0, SBYTES);
        BULK_G2S(smem_u32(Bf2), bsrc, SBYTES, mb0);
    }

    // first sine layer -> A buffer (fragment-paired layout)
    {
        const float* W1e = sW1 + (size_t)e * 3 * F_DIM;
        const float* b1e = sb1 + (size_t)e * F_DIM;
        float* A0 = (float*)Af2;
        for (int idx = tid; idx < TMS * 240; idx += 256) {
            int row = idx / 240, col = idx - row * 240;
            float v = 0.f;
            if (col < F_DIM) {
                v = xs[row * 3] * tf32q(W1e[col])
                  + xs[row * 3 + 1] * tf32q(W1e[F_DIM + col])
                  + xs[row * 3 + 2] * tf32q(W1e[2 * F_DIM + col])
                  + b1e[col];
                v = tf32q(sinf(30.0f * v));
            }
            A0[(((col >> 3) * TMS + row) * 4 + (col & 3)) * 2 + ((col >> 2) & 1)] = v;
        }
    }
    __syncthreads();

    int ci = 0;
#pragma unroll 1
    for (int l = 0; l < NLAYER; l++) {
        float acc[2][15][4];
#pragma unroll
        for (int m = 0; m < 2; m++)
#pragma unroll
            for (int nb = 0; nb < 15; nb++)
#pragma unroll
                for (int j = 0; j < 4; j++) acc[m][nb][j] = 0.f;

#pragma unroll 1
        for (int chn = 0; chn < SNCH; chn++, ci++) {
            const int s = ci & 1, ph = (ci >> 1) & 1;
            MBAR_WAIT(mb0 + 8 * s, ph);
            __syncthreads();
            if (ci + 1 < NLAYER * SNCH && tid == 0) {
                const int t = s ^ 1;
                MBAR_EXPECT_TX(mb0 + 8 * t, SBYTES);
                BULK_G2S(smem_u32(Bf2 + t * SSLAB), bsrc + (size_t)(ci + 1) * SBYTES, SBYTES, mb0 + 8 * t);
            }
            const float2* Bb = Bf2 + s * SSLAB;
#pragma unroll
            for (int ksl = 0; ksl < SKC; ksl++) {
                int kg = chn * SKC + ksl;
                uint32_t a[2][4];
#pragma unroll
                for (int mb = 0; mb < 2; mb++) {
                    int r = wrow + 16 * mb + r4;
                    float2 p = Af2[(kg * TMS + r) * 4 + c4];
                    float2 q = Af2[(kg * TMS + r + 8) * 4 + c4];
                    a[mb][0] = f2u(p.x); a[mb][1] = f2u(q.x);
                    a[mb][2] = f2u(p.y); a[mb][3] = f2u(q.y);
                }
#pragma unroll
                for (int nb = 0; nb < 15; nb++) {
                    float2 b = Bb[(ksl * 4 + c4) * SNPAD + wcol + nb * 8 + r4];
                    mma8(acc[0][nb], a[0], f2u(b.x), f2u(b.y));
                    mma8(acc[1][nb], a[1], f2u(b.x), f2u(b.y));
                }
            }
        }

        if (l < 4) {
            // in-place epilogue: warp owns its 32 rows; all its A reads are done
            const float* bias = (l < 3) ? (sbh + (size_t)(l * E_EXP + e) * F_DIM)
                                        : (sbo + (size_t)e * F_DIM);
            float* Cw = (float*)Af2;
#pragma unroll
            for (int mb = 0; mb < 2; mb++) {
                int r = wrow + 16 * mb + r4;
#pragma unroll
                for (int nb = 0; nb < 15; nb++) {
                    int j0 = wcol + nb * 8 + 2 * c4;
                    int kt = j0 >> 3, cA = j0 & 3, h = (j0 >> 2) & 1;
#pragma unroll
                    for (int hr = 0; hr < 2; hr++) {
                        int row = r + 8 * hr;
                        float v0 = 0.f, v1 = 0.f;
                        if (j0 < F_DIM) {
                            v0 = acc[mb][nb][2 * hr] + bias[j0];
                            if (l < 3) v0 = sinf(30.0f * v0);
                            v0 = tf32q(v0);
                        }
                        if (j0 + 1 < F_DIM) {
                            v1 = acc[mb][nb][2 * hr + 1] + bias[j0 + 1];
                            if (l < 3) v1 = sinf(30.0f * v1);
                            v1 = tf32q(v1);
                        }
                        int base = ((kt * TMS + row) * 4 + cA) * 2 + h;
                        Cw[base] = v0;
                        Cw[base + 2] = v1;
                    }
                }
            }
        } else {
            // dec1 (relu) + dec2 (236->3) fused from registers
            float s[4][3];
#pragma unroll
            for (int ri = 0; ri < 4; ri++)
#pragma unroll
                for (int o = 0; o < 3; o++) s[ri][o] = 0.f;
#pragma unroll
            for (int mb = 0; mb < 2; mb++) {
#pragma unroll
                for (int nb = 0; nb < 15; nb++) {
                    int j0 = wcol + nb * 8 + 2 * c4;
                    if (j0 >= F_DIM) continue;
#pragma unroll
                    for (int hr = 0; hr < 2; hr++) {
                        int ri = mb * 2 + hr;
                        float a0 = tf32q(fmaxf(acc[mb][nb][2 * hr] + db1[j0], 0.f));
                        s[ri][0] = fmaf(a0, tf32q(dW2[j0 * 3 + 0]), s[ri][0]);
                        s[ri][1] = fmaf(a0, tf32q(dW2[j0 * 3 + 1]), s[ri][1]);
                        s[ri][2] = fmaf(a0, tf32q(dW2[j0 * 3 + 2]), s[ri][2]);
                        if (j0 + 1 < F_DIM) {
                            float a1 = tf32q(fmaxf(acc[mb][nb][2 * hr + 1] + db1[j0 + 1], 0.f));
                            s[ri][0] = fmaf(a1, tf32q(dW2[(j0 + 1) * 3 + 0]), s[ri][0]);
                            s[ri][1] = fmaf(a1, tf32q(dW2[(j0 + 1) * 3 + 1]), s[ri][1]);
                            s[ri][2] = fmaf(a1, tf32q(dW2[(j0 + 1) * 3 + 2]), s[ri][2]);
                        }
                    }
                }
            }
#pragma unroll
            for (int ri = 0; ri < 4; ri++)
#pragma unroll
                for (int o = 0; o < 3; o++) {
                    float v = s[ri][o];
                    v += __shfl_xor_sync(0xffffffffu, v, 1);
                    v += __shfl_xor_sync(0xffffffffu, v, 2);
                    s[ri][o] = v;
                }
            if (c4 == 0) {
#pragma unroll
                for (int ri = 0; ri < 4; ri++) {
                    int row = wrow + 16 * (ri >> 1) + r4 + 8 * (ri & 1);
#pragma unroll
                    for (int o = 0; o < 3; o++) part[ng][row][o] = s[ri][o];
                }
            }
            __syncthreads();
            for (int idx = tid; idx < TMS * 3; idx += 256) {
                int p = idx / 3, o = idx - p * 3;
                if (p < npts) {
                    float v = db2[o] + part[0][p][o] + part[1][p][o];
                    out[g_perm[start + p] * 3 + o] = v;
                }
            }
        }
    }
}

// ---------------- launch ----------------
extern "C" void kernel_launch(void* const* d_in, const int* in_sizes, int n_in,
                              void* d_out, int out_size)
{
    const float* x   = (const float*)d_in[0];
    const float* sW1 = (const float*)d_in[1];
    const float* sb1 = (const float*)d_in[2];
    const float* sWh = (const float*)d_in[3];
    const float* sbh = (const float*)d_in[4];
    const float* sWo = (const float*)d_in[5];
    const float* sbo = (const float*)d_in[6];
    const float* mW1 = (const float*)d_in[7];
    const float* mb1 = (const float*)d_in[8];
    const float* mW2 = (const float*)d_in[9];
    const float* mb2 = (const float*)d_in[10];
    const float* mW3 = (const float*)d_in[11];
    const float* mb3 = (const float*)d_in[12];
    const float* dW1 = (const float*)d_in[13];
    const float* db1 = (const float*)d_in[14];
    const float* dW2 = (const float*)d_in[15];
    const float* db2 = (const float*)d_in[16];
    float* out = (float*)d_out;

    size_t smem_gate  = (size_t)(2 * GASLAB + 2 * GBSLAB) * 8;  // 62464 B
    size_t smem_siren = (size_t)(SABUF + 2 * SSLAB) * 8;        // 206080 B
    cudaFuncSetAttribute(k_gate,  cudaFuncAttributeMaxDynamicSharedMemorySize, (int)smem_gate);
    cudaFuncSetAttribute(k_siren, cudaFuncAttributeMaxDynamicSharedMemorySize, (int)smem_siren);

    k_init<<<1, 32>>>();
    k_g1<<<512, 256>>>(x, mW1, mb1);
    k_prep_gateB<<<256, 256>>>(mW2);
    k_prep_siren<<<E_EXP * NLAYER * 8, 256>>>(sWh, sWo, dW1);

    dim3 gG(4, 512);                         // (N tiles, bands)
    k_gate<<<gG, 256, smem_gate>>>(mb2, mW3);

    k_argmax<<<N_PTS / 256, 256>>>(mb3);

    k_scan<<<1, 32>>>(out, out_size - 1);

    k_scatter<<<N_PTS / 256, 256>>>();

    dim3 gS((N_PTS + TMS - 1) / TMS, E_EXP); // (512, 8), extras exit
    k_siren<<<gS, 256, smem_siren>>>(x, sW1, sb1, sbh, sbo, db1, dW2, db2, out);
}

// round 12
// speedup vs baseline: 1.3492x; 1.3492x over previous
#include <cuda_runtime.h>
#include <math.h>
#include <stdint.h>

#define N_PTS 65536
#define E_EXP 8
#define F_DIM 236
#define M_DIM 441
#define NLAYER 5

// ---- siren tiling ----
#define TMS   128           // points per CTA
#define STHREADS 512        // 16 warps: 4M x 4N
#define SKS   30            // total ksteps (K padded 240)
#define SKC   5             // ksteps per B chunk
#define SNCH  6             // chunks per layer
#define SNPAD 260           // B n-pad (f2 row len)
#define SSLAB (SKC*4*SNPAD) // 5200 f2 per B slab (41600 B)
#define SABUF (SKS*TMS*4)   // 15360 f2, single in-place A buffer
#define SBYTES (SSLAB*8)

// ---- gate tiling ----
#define GM    128
#define GNT   112
#define GKC   4             // ksteps per chunk
#define GNCH  14            // K padded 448
#define GNPAD 116
#define GASLAB (GKC*GM*4)    // 2048 f2 (16384 B)
#define GBSLAB (GKC*4*GNPAD) // 1856 f2 (14848 B)
#define GBYTES (GASLAB*8 + GBSLAB*8)

// ---------------- helpers ----------------
__device__ __forceinline__ float tf32q(float x) {
    float r; asm("cvt.rna.tf32.f32 %0, %1;" : "=f"(r) : "f"(x)); return r;
}
__device__ __forceinline__ uint32_t smem_u32(const void* p) {
    uint32_t a;
    asm("{ .reg .u64 t; cvta.to.shared.u64 t, %1; cvt.u32.u64 %0, t; }" : "=r"(a) : "l"(p));
    return a;
}
#define MBAR_INIT(a, n)  asm volatile("mbarrier.init.shared.b64 [%0], %1;" :: "r"(a), "r"((uint32_t)(n)) : "memory")
#define MBAR_EXPECT_TX(a, n) asm volatile("mbarrier.arrive.expect_tx.shared.b64 _, [%0], %1;" :: "r"(a), "r"((uint32_t)(n)) : "memory")
#define MBAR_WAIT(a, ph) do {                                                   \
    uint32_t _m = (a); uint32_t _p = (ph); uint32_t _d;                         \
    asm volatile("{\n\t.reg .pred p;\n\t"                                       \
        "mbarrier.try_wait.parity.acquire.cta.shared::cta.b64 p, [%1], %2;\n\t" \
        "selp.b32 %0, 1, 0, p;\n\t}" : "=r"(_d) : "r"(_m), "r"(_p) : "memory"); \
    if (!_d) {                                                                  \
        asm volatile("{\n\t.reg .pred P1;\n\t"                                  \
            "W%=:\n\t"                                                          \
            "mbarrier.try_wait.parity.acquire.cta.shared::cta.b64 P1, [%0], %1, 0x989680;\n\t" \
            "@P1 bra.uni D%=;\n\t"                                              \
            "bra.uni W%=;\n\t"                                                  \
            "D%=:\n\t}" :: "r"(_m), "r"(_p) : "memory");                        \
    } } while (0)
#define BULK_G2S(dst, src, bytes, mbar) \
    asm volatile("cp.async.bulk.shared::cluster.global.mbarrier::complete_tx::bytes [%0], [%1], %2, [%3];" \
        :: "r"(dst), "l"(src), "r"((uint32_t)(bytes)), "r"(mbar) : "memory")
#define REDADD(addr, v) \
    asm volatile("red.global.add.f32 [%0], %1;" :: "l"(addr), "f"(v) : "memory")

__device__ __forceinline__ void mma8(float* d, const uint32_t* a, uint32_t b0, uint32_t b1) {
    asm volatile(
        "mma.sync.aligned.m16n8k8.row.col.f32.tf32.tf32.f32 "
        "{%0,%1,%2,%3}, {%4,%5,%6,%7}, {%8,%9}, {%0,%1,%2,%3};"
        : "+f"(d[0]), "+f"(d[1]), "+f"(d[2]), "+f"(d[3])
        : "r"(a[0]), "r"(a[1]), "r"(a[2]), "r"(a[3]), "r"(b0), "r"(b1));
}
__device__ __forceinline__ uint32_t f2u(float f) { return __float_as_uint(f); }

// -------- device scratch --------
__device__ float g_logits[N_PTS * E_EXP];
__device__ int   g_expert[N_PTS];
__device__ int   g_counts[E_EXP];
__device__ int   g_offsets[E_EXP + 1];
__device__ int   g_cursor[E_EXP];
__device__ int   g_perm[N_PTS];
// g1 activations, A-fragment-paired: [band512][ch14][GASLAB f2]
__device__ __align__(16) float g_g1p[(size_t)512 * GNCH * GASLAB * 2];
// gate W2, bulk-ready: [tile4][ch14][GBSLAB f2]
__device__ __align__(16) float g_W2t[4 * GNCH * GBSLAB * 2];
// siren weights paired: [e][l][ch6][SSLAB f2]
__device__ __align__(16) float g_Bws[E_EXP * NLAYER * SNCH * SSLAB * 2];

// ---------------- init ----------------
__global__ void k_init() {
    int t = threadIdx.x;
    if (t < E_EXP) g_counts[t] = 0;
}

// ---------------- g1 precompute (paired A layout) + zero logits ----------------
__global__ void __launch_bounds__(256) k_g1(
    const float* __restrict__ x, const float* __restrict__ W1, const float* __restrict__ b1)
{
    __shared__ float xs[GM * 3];
    int band = blockIdx.x;
    for (int i = threadIdx.x; i < GM * 3; i += 256) xs[i] = tf32q(x[band * GM * 3 + i]);
    for (int i = threadIdx.x; i < GM * E_EXP; i += 256) g_logits[band * GM * E_EXP + i] = 0.f;
    __syncthreads();
    float2* dst = ((float2*)g_g1p) + (size_t)band * (GNCH * GASLAB);
    for (int s = threadIdx.x; s < 56 * GM * 4; s += 256) {
        int c = s & 3, r = (s >> 2) & 127, kt = s >> 9;    // kt 0..55
        int k0 = kt * 8 + c;
        const float* xr = xs + r * 3;
        float2 v; v.x = 0.f; v.y = 0.f;
        if (k0 < M_DIM)
            v.x = tf32q(fmaxf(xr[0] * tf32q(W1[k0]) + xr[1] * tf32q(W1[M_DIM + k0])
                            + xr[2] * tf32q(W1[2 * M_DIM + k0]) + b1[k0], 0.f));
        int k1 = k0 + 4;
        if (k1 < M_DIM)
            v.y = tf32q(fmaxf(xr[0] * tf32q(W1[k1]) + xr[1] * tf32q(W1[M_DIM + k1])
                            + xr[2] * tf32q(W1[2 * M_DIM + k1]) + b1[k1], 0.f));
        dst[s] = v;
    }
}

// ---------------- weight preps ----------------
__global__ void k_prep_gateB(const float* __restrict__ W2) {
    float2* dst = (float2*)g_W2t;
    const int total = 4 * GNCH * GBSLAB;
    for (int s = blockIdx.x * blockDim.x + threadIdx.x; s < total;
         s += gridDim.x * blockDim.x) {
        int n = s % GNPAD;
        int c = (s / GNPAD) & 3;
        int ks = (s / (GNPAD * 4)) & 3;
        int ch = (s / (GNPAD * 16)) % GNCH;
        int tile = s / (GNPAD * 16 * GNCH);
        int k0 = (ch * 4 + ks) * 8 + c;
        int col = tile * GNT + n;
        float2 v; v.x = 0.f; v.y = 0.f;
        if (n < GNT && col < M_DIM) {
            if (k0 < M_DIM)     v.x = tf32q(W2[(size_t)k0 * M_DIM + col]);
            if (k0 + 4 < M_DIM) v.y = tf32q(W2[(size_t)(k0 + 4) * M_DIM + col]);
        }
        dst[s] = v;
    }
}
__global__ void k_prep_siren(const float* __restrict__ sWh,
                             const float* __restrict__ sWo,
                             const float* __restrict__ dW1)
{
    int el = blockIdx.x >> 3;             // 0..39
    int part = blockIdx.x & 7;
    int e = el / NLAYER, l = el % NLAYER;
    const float* W;
    if (l < 3)       W = sWh + ((size_t)(l * E_EXP + e)) * F_DIM * F_DIM;
    else if (l == 3) W = sWo + (size_t)e * F_DIM * F_DIM;
    else             W = dW1 + (size_t)e * F_DIM * F_DIM;
    float2* dst = ((float2*)g_Bws) + (size_t)el * (SNCH * SSLAB);
    for (int s = part * 256 + threadIdx.x; s < SNCH * SSLAB; s += 2048) {
        int n = s % SNPAD, c = (s / SNPAD) & 3, ks = (s / (SNPAD * 4)) % 5, ch = s / SSLAB;
        int k0 = (ch * SKC + ks) * 8 + c;
        float2 v; v.x = 0.f; v.y = 0.f;
        if (n < F_DIM) {
            if (k0 < F_DIM)     v.x = tf32q(W[k0 * F_DIM + n]);
            if (k0 + 4 < F_DIM) v.y = tf32q(W[(k0 + 4) * F_DIM + n]);
        }
        dst[s] = v;
    }
}

// ---------------- gating GEMM + fused partial logits ----------------
__global__ void __launch_bounds__(256, 2) k_gate(
    const float* __restrict__ b2, const float* __restrict__ W3)
{
    extern __shared__ float smf[];
    float2* Af = (float2*)smf;                 // 2 x GASLAB
    float2* Bf = ((float2*)smf) + 2 * GASLAB;  // 2 x GBSLAB
    __shared__ __align__(8) unsigned long long mbar[2];
    const int tid = threadIdx.x;
    const int wid = tid >> 5, lane = tid & 31;
    const int r4 = lane >> 2, c4 = lane & 3;
    const int band = blockIdx.y;
    const int tile = blockIdx.x;
    const int wrow = (wid & 3) * 32;
    const int wcol = (wid >> 2) * 56;
    const uint32_t mb0 = smem_u32(&mbar[0]);

    const char* srcA = (const char*)g_g1p + (size_t)band * GNCH * (GASLAB * 8);
    const char* srcB = (const char*)g_W2t + (size_t)tile * GNCH * (GBSLAB * 8);

    float acc[2][7][4];
#pragma unroll
    for (int m = 0; m < 2; m++)
#pragma unroll
        for (int nb = 0; nb < 7; nb++)
#pragma unroll
            for (int j = 0; j < 4; j++) acc[m][nb][j] = 0.f;

    if (tid == 0) { MBAR_INIT(mb0, 1); MBAR_INIT(mb0 + 8, 1); }
    __syncthreads();
    if (tid == 0) {
        MBAR_EXPECT_TX(mb0, GBYTES);
        BULK_G2S(smem_u32(Af), srcA, GASLAB * 8, mb0);
        BULK_G2S(smem_u32(Bf), srcB, GBSLAB * 8, mb0);
    }

#pragma unroll 1
    for (int ch = 0; ch < GNCH; ch++) {
        const int s = ch & 1, ph = (ch >> 1) & 1;
        MBAR_WAIT(mb0 + 8 * s, ph);
        __syncthreads();
        if (ch + 1 < GNCH && tid == 0) {
            const int t = s ^ 1;
            MBAR_EXPECT_TX(mb0 + 8 * t, GBYTES);
            BULK_G2S(smem_u32(Af + t * GASLAB), srcA + (size_t)(ch + 1) * GASLAB * 8, GASLAB * 8, mb0 + 8 * t);
            BULK_G2S(smem_u32(Bf + t * GBSLAB), srcB + (size_t)(ch + 1) * GBSLAB * 8, GBSLAB * 8, mb0 + 8 * t);
        }
        const float2* Ab = Af + s * GASLAB;
        const float2* Bb = Bf + s * GBSLAB;
#pragma unroll
        for (int ks = 0; ks < GKC; ks++) {
            uint32_t a[2][4];
#pragma unroll
            for (int mb = 0; mb < 2; mb++) {
                int r = wrow + 16 * mb + r4;
                float2 p = Ab[(ks * GM + r) * 4 + c4];
                float2 q = Ab[(ks * GM + r + 8) * 4 + c4];
                a[mb][0] = f2u(p.x); a[mb][1] = f2u(q.x);
                a[mb][2] = f2u(p.y); a[mb][3] = f2u(q.y);
            }
#pragma unroll
            for (int nb = 0; nb < 7; nb++) {
                float2 b = Bb[(ks * 4 + c4) * GNPAD + wcol + nb * 8 + r4];
                mma8(acc[0][nb], a[0], f2u(b.x), f2u(b.y));
                mma8(acc[1][nb], a[1], f2u(b.x), f2u(b.y));
            }
        }
    }

    // fused epilogue: g2 = tf32q(relu(acc+b2)); partial logits = g2 . W3
    float s[4][8];
#pragma unroll
    for (int ri = 0; ri < 4; ri++)
#pragma unroll
        for (int ee = 0; ee < 8; ee++) s[ri][ee] = 0.f;
#pragma unroll
    for (int mb = 0; mb < 2; mb++) {
#pragma unroll
        for (int nb = 0; nb < 7; nb++) {
#pragma unroll
            for (int h = 0; h < 2; h++) {
                int col = tile * GNT + wcol + nb * 8 + 2 * c4 + h;
                if (col < M_DIM) {
                    float4 wa = *(const float4*)(W3 + col * 8);
                    float4 wb = *(const float4*)(W3 + col * 8 + 4);
                    float bb = b2[col];
#pragma unroll
                    for (int hr = 0; hr < 2; hr++) {
                        int ri = mb * 2 + hr;
                        float g = tf32q(fmaxf(acc[mb][nb][2 * hr + h] + bb, 0.f));
                        s[ri][0] = fmaf(g, tf32q(wa.x), s[ri][0]);
                        s[ri][1] = fmaf(g, tf32q(wa.y), s[ri][1]);
                        s[ri][2] = fmaf(g, tf32q(wa.z), s[ri][2]);
                        s[ri][3] = fmaf(g, tf32q(wa.w), s[ri][3]);
                        s[ri][4] = fmaf(g, tf32q(wb.x), s[ri][4]);
                        s[ri][5] = fmaf(g, tf32q(wb.y), s[ri][5]);
                        s[ri][6] = fmaf(g, tf32q(wb.z), s[ri][6]);
                        s[ri][7] = fmaf(g, tf32q(wb.w), s[ri][7]);
                    }
                }
            }
        }
    }
#pragma unroll
    for (int ri = 0; ri < 4; ri++)
#pragma unroll
        for (int ee = 0; ee < 8; ee++) {
            float v = s[ri][ee];
            v += __shfl_xor_sync(0xffffffffu, v, 1);
            v += __shfl_xor_sync(0xffffffffu, v, 2);
            s[ri][ee] = v;
        }
    if (c4 == 0) {
#pragma unroll
        for (int ri = 0; ri < 4; ri++) {
            int row = band * GM + wrow + 16 * (ri >> 1) + r4 + 8 * (ri & 1);
            float* dst = g_logits + (size_t)row * 8;
#pragma unroll
            for (int ee = 0; ee < 8; ee++) REDADD(dst + ee, s[ri][ee]);
        }
    }
}

// ---------------- argmax over fused logits ----------------
__global__ void __launch_bounds__(256) k_argmax(const float* __restrict__ b3) {
    int n = blockIdx.x * blockDim.x + threadIdx.x;
    if (n >= N_PTS) return;
    const float* lg = g_logits + (size_t)n * 8;
    float best = lg[0] + b3[0]; int bi = 0;
#pragma unroll
    for (int e = 1; e < 8; e++) {
        float v = lg[e] + b3[e];
        if (v > best) { best = v; bi = e; }
    }
    g_expert[n] = bi;
    atomicAdd(&g_counts[bi], 1);
}

// ---------------- scan + KL (one-hot => constant) ----------------
__global__ void k_scan(float* out, int kl_idx) {
    if (threadIdx.x == 0) {
        int off = 0;
        for (int e = 0; e < E_EXP; e++) {
            g_offsets[e] = off;
            off += g_counts[e];
            g_cursor[e] = 0;
        }
        g_offsets[E_EXP] = off;
        out[kl_idx] = logf(0.125f) - 0.875f * logf(1e-10f);
    }
}

// ---------------- scatter ----------------
__global__ void k_scatter() {
    int n = blockIdx.x * blockDim.x + threadIdx.x;
    if (n >= N_PTS) return;
    int e = g_expert[n];
    int p = atomicAdd(&g_cursor[e], 1);
    g_perm[g_offsets[e] + p] = n;
}

// ---------------- fused SIREN + decoder (tf32 mma, in-place A, 512 thr) ----------------
// TMS=128 points per CTA, 16 warps = 4M x 4N, warp tile 32x64 (acc 64 regs).
// Single in-place A buffer: __syncthreads() between last MMA read and epilogue
// writes makes the N-split overwrite safe.
__global__ void __launch_bounds__(STHREADS, 1) k_siren(
    const float* __restrict__ x,
    const float* __restrict__ sW1, const float* __restrict__ sb1,
    const float* __restrict__ sbh, const float* __restrict__ sbo,
    const float* __restrict__ db1,
    const float* __restrict__ dW2, const float* __restrict__ db2,
    float* __restrict__ out)
{
    extern __shared__ float smf[];
    float2* Af2 = (float2*)smf;              // SABUF (in-place)
    float2* Bf2 = Af2 + SABUF;               // 2 x SSLAB
    __shared__ float xs[TMS * 3];
    __shared__ float part[4][TMS][3];
    __shared__ __align__(8) unsigned long long mbar[2];

    const int e = blockIdx.y;
    const int tid = threadIdx.x;
    const int wid = tid >> 5, lane = tid & 31;
    const int r4 = lane >> 2, c4 = lane & 3;
    const int beg = g_offsets[e], end = g_offsets[e + 1];
    const int start = beg + blockIdx.x * TMS;
    if (start >= end) return;
    const int npts = min(TMS, end - start);
    const uint32_t mb0 = smem_u32(&mbar[0]);

    const int wrow = (wid & 3) * 32;
    const int ng = wid >> 2;                 // 0..3
    const int wcol = ng * 64;
    const char* bsrc = (const char*)g_Bws + (size_t)e * (NLAYER * SNCH) * SBYTES;

    if (tid == 0) { MBAR_INIT(mb0, 1); MBAR_INIT(mb0 + 8, 1); }
    if (tid < TMS) {
        float x0 = 0.f, x1 = 0.f, x2 = 0.f;
        if (tid < npts) {
            int n = g_perm[start + tid];
            x0 = tf32q(x[n * 3]); x1 = tf32q(x[n * 3 + 1]); x2 = tf32q(x[n * 3 + 2]);
        }
        xs[tid * 3] = x0; xs[tid * 3 + 1] = x1; xs[tid * 3 + 2] = x2;
    }
    __syncthreads();
    if (tid == 0) {
        MBAR_EXPECT_TX(mb0, SBYTES);
        BULK_G2S(smem_u32(Bf2), bsrc, SBYTES, mb0);
    }

    // first sine layer -> A buffer (fragment-paired layout)
    {
        const float* W1e = sW1 + (size_t)e * 3 * F_DIM;
        const float* b1e = sb1 + (size_t)e * F_DIM;
        float* A0 = (float*)Af2;
        for (int idx = tid; idx < TMS * 240; idx += STHREADS) {
            int row = idx / 240, col = idx - row * 240;
            float v = 0.f;
            if (col < F_DIM) {
                v = xs[row * 3] * tf32q(W1e[col])
                  + xs[row * 3 + 1] * tf32q(W1e[F_DIM + col])
                  + xs[row * 3 + 2] * tf32q(W1e[2 * F_DIM + col])
                  + b1e[col];
                v = tf32q(sinf(30.0f * v));
            }
            A0[(((col >> 3) * TMS + row) * 4 + (col & 3)) * 2 + ((col >> 2) & 1)] = v;
        }
    }
    __syncthreads();

    int ci = 0;
#pragma unroll 1
    for (int l = 0; l < NLAYER; l++) {
        float acc[2][8][4];
#pragma unroll
        for (int m = 0; m < 2; m++)
#pragma unroll
            for (int nb = 0; nb < 8; nb++)
#pragma unroll
                for (int j = 0; j < 4; j++) acc[m][nb][j] = 0.f;

#pragma unroll 1
        for (int chn = 0; chn < SNCH; chn++, ci++) {
            const int s = ci & 1, ph = (ci >> 1) & 1;
            MBAR_WAIT(mb0 + 8 * s, ph);
            __syncthreads();
            if (ci + 1 < NLAYER * SNCH && tid == 0) {
                const int t = s ^ 1;
                MBAR_EXPECT_TX(mb0 + 8 * t, SBYTES);
                BULK_G2S(smem_u32(Bf2 + t * SSLAB), bsrc + (size_t)(ci + 1) * SBYTES, SBYTES, mb0 + 8 * t);
            }
            const float2* Bb = Bf2 + s * SSLAB;
#pragma unroll
            for (int ksl = 0; ksl < SKC; ksl++) {
                int kg = chn * SKC + ksl;
                uint32_t a[2][4];
#pragma unroll
                for (int mb = 0; mb < 2; mb++) {
                    int r = wrow + 16 * mb + r4;
                    float2 p = Af2[(kg * TMS + r) * 4 + c4];
                    float2 q = Af2[(kg * TMS + r + 8) * 4 + c4];
                    a[mb][0] = f2u(p.x); a[mb][1] = f2u(q.x);
                    a[mb][2] = f2u(p.y); a[mb][3] = f2u(q.y);
                }
#pragma unroll
                for (int nb = 0; nb < 8; nb++) {
                    float2 b = Bb[(ksl * 4 + c4) * SNPAD + wcol + nb * 8 + r4];
                    mma8(acc[0][nb], a[0], f2u(b.x), f2u(b.y));
                    mma8(acc[1][nb], a[1], f2u(b.x), f2u(b.y));
                }
            }
        }

        if (l < 4) {
            // All MMA reads of A (this layer) must drain before in-place writes:
            __syncthreads();
            const float* bias = (l < 3) ? (sbh + (size_t)(l * E_EXP + e) * F_DIM)
                                        : (sbo + (size_t)e * F_DIM);
            float* Cw = (float*)Af2;
#pragma unroll
            for (int mb = 0; mb < 2; mb++) {
                int r = wrow + 16 * mb + r4;
#pragma unroll
                for (int nb = 0; nb < 8; nb++) {
                    int j0 = wcol + nb * 8 + 2 * c4;
                    if (j0 >= 240) continue;
                    int kt = j0 >> 3, cA = j0 & 3, h = (j0 >> 2) & 1;
#pragma unroll
                    for (int hr = 0; hr < 2; hr++) {
                        int row = r + 8 * hr;
                        float v0 = 0.f, v1 = 0.f;
                        if (j0 < F_DIM) {
                            v0 = acc[mb][nb][2 * hr] + bias[j0];
                            if (l < 3) v0 = sinf(30.0f * v0);
                            v0 = tf32q(v0);
                        }
                        if (j0 + 1 < F_DIM) {
                            v1 = acc[mb][nb][2 * hr + 1] + bias[j0 + 1];
                            if (l < 3) v1 = sinf(30.0f * v1);
                            v1 = tf32q(v1);
                        }
                        int base = ((kt * TMS + row) * 4 + cA) * 2 + h;
                        Cw[base] = v0;
                        Cw[base + 2] = v1;
                    }
                }
            }
        } else {
            // dec1 (relu) + dec2 (236->3) fused from registers
            float s[4][3];
#pragma unroll
            for (int ri = 0; ri < 4; ri++)
#pragma unroll
                for (int o = 0; o < 3; o++) s[ri][o] = 0.f;
#pragma unroll
            for (int mb = 0; mb < 2; mb++) {
#pragma unroll
                for (int nb = 0; nb < 8; nb++) {
                    int j0 = wcol + nb * 8 + 2 * c4;
                    if (j0 >= F_DIM) continue;
#pragma unroll
                    for (int hr = 0; hr < 2; hr++) {
                        int ri = mb * 2 + hr;
                        float a0 = tf32q(fmaxf(acc[mb][nb][2 * hr] + db1[j0], 0.f));
                        s[ri][0] = fmaf(a0, tf32q(dW2[j0 * 3 + 0]), s[ri][0]);
                        s[ri][1] = fmaf(a0, tf32q(dW2[j0 * 3 + 1]), s[ri][1]);
                        s[ri][2] = fmaf(a0, tf32q(dW2[j0 * 3 + 2]), s[ri][2]);
                        if (j0 + 1 < F_DIM) {
                            float a1 = tf32q(fmaxf(acc[mb][nb][2 * hr + 1] + db1[j0 + 1], 0.f));
                            s[ri][0] = fmaf(a1, tf32q(dW2[(j0 + 1) * 3 + 0]), s[ri][0]);
                            s[ri][1] = fmaf(a1, tf32q(dW2[(j0 + 1) * 3 + 1]), s[ri][1]);
                            s[ri][2] = fmaf(a1, tf32q(dW2[(j0 + 1) * 3 + 2]), s[ri][2]);
                        }
                    }
                }
            }
#pragma unroll
            for (int ri = 0; ri < 4; ri++)
#pragma unroll
                for (int o = 0; o < 3; o++) {
                    float v = s[ri][o];
                    v += __shfl_xor_sync(0xffffffffu, v, 1);
                    v += __shfl_xor_sync(0xffffffffu, v, 2);
                    s[ri][o] = v;
                }
            if (c4 == 0) {
#pragma unroll
                for (int ri = 0; ri < 4; ri++) {
                    int row = wrow + 16 * (ri >> 1) + r4 + 8 * (ri & 1);
#pragma unroll
                    for (int o = 0; o < 3; o++) part[ng][row][o] = s[ri][o];
                }
            }
            __syncthreads();
            for (int idx = tid; idx < TMS * 3; idx += STHREADS) {
                int p = idx / 3, o = idx - p * 3;
                if (p < npts) {
                    float v = db2[o] + part[0][p][o] + part[1][p][o]
                            + part[2][p][o] + part[3][p][o];
                    out[g_perm[start + p] * 3 + o] = v;
                }
            }
        }
    }
}

// ---------------- launch ----------------
extern "C" void kernel_launch(void* const* d_in, const int* in_sizes, int n_in,
                              void* d_out, int out_size)
{
    const float* x   = (const float*)d_in[0];
    const float* sW1 = (const float*)d_in[1];
    const float* sb1 = (const float*)d_in[2];
    const float* sWh = (const float*)d_in[3];
    const float* sbh = (const float*)d_in[4];
    const float* sWo = (const float*)d_in[5];
    const float* sbo = (const float*)d_in[6];
    const float* mW1 = (const float*)d_in[7];
    const float* mb1 = (const float*)d_in[8];
    const float* mW2 = (const float*)d_in[9];
    const float* mb2 = (const float*)d_in[10];
    const float* mW3 = (const float*)d_in[11];
    const float* mb3 = (const float*)d_in[12];
    const float* dW1 = (const float*)d_in[13];
    const float* db1 = (const float*)d_in[14];
    const float* dW2 = (const float*)d_in[15];
    const float* db2 = (const float*)d_in[16];
    float* out = (float*)d_out;

    size_t smem_gate  = (size_t)(2 * GASLAB + 2 * GBSLAB) * 8;  // 62464 B
    size_t smem_siren = (size_t)(SABUF + 2 * SSLAB) * 8;        // 206080 B
    cudaFuncSetAttribute(k_gate,  cudaFuncAttributeMaxDynamicSharedMemorySize, (int)smem_gate);
    cudaFuncSetAttribute(k_siren, cudaFuncAttributeMaxDynamicSharedMemorySize, (int)smem_siren);

    k_init<<<1, 32>>>();
    k_g1<<<512, 256>>>(x, mW1, mb1);
    k_prep_gateB<<<256, 256>>>(mW2);
    k_prep_siren<<<E_EXP * NLAYER * 8, 256>>>(sWh, sWo, dW1);

    dim3 gG(4, 512);                         // (N tiles, bands)
    k_gate<<<gG, 256, smem_gate>>>(mb2, mW3);

    k_argmax<<<N_PTS / 256, 256>>>(mb3);

    k_scan<<<1, 32>>>(out, out_size - 1);

    k_scatter<<<N_PTS / 256, 256>>>();

    dim3 gS((N_PTS + TMS - 1) / TMS, E_EXP); // (512, 8), extras exit
    k_siren<<<gS, STHREADS, smem_siren>>>(x, sW1, sb1, sbh, sbo, db1, dW2, db2, out);
}

// round 13
// speedup vs baseline: 1.8626x; 1.3806x over previous
#include <cuda_runtime.h>
#include <cuda_fp16.h>
#include <math.h>
#include <stdint.h>

#define N_PTS 65536
#define E_EXP 8
#define F_DIM 236
#define M_DIM 441
#define NLAYER 5

// ---- siren tiling (fp16 k16) ----
#define TMS   128           // points per CTA
#define STHREADS 512        // 16 warps: 4M x 4N
#define SKT   15            // ksteps of 16 (K padded 240)
#define SKC   5             // ksteps per B chunk
#define SNCH  3             // chunks per layer
#define NCI   (NLAYER*SNCH) // 15
#define SNPAD 260           // B n-pad (uint2 row len)
#define SSLAB_U2 (SKC*4*SNPAD)  // 5200 uint2 (41600 B)
#define SABUF_U2 (SKT*TMS*4)    // 7680 uint2 (61440 B)
#define SBYTES (SSLAB_U2*8)

// ---- gate tiling (fp16 k16) ----
#define GM    128
#define GNT   112
#define GKC   4             // ksteps per chunk
#define GNCH  7             // 7*4*16 = 448 >= 441
#define GNPAD 116
#define GASLAB_U2 (GKC*GM*4)    // 2048 uint2 (16384 B)
#define GBSLAB_U2 (GKC*4*GNPAD) // 1856 uint2 (14848 B)
#define GBYTES (GASLAB_U2*8 + GBSLAB_U2*8)

// ---------------- helpers ----------------
__device__ __forceinline__ float tf32q(float x) {
    float r; asm("cvt.rna.tf32.f32 %0, %1;" : "=f"(r) : "f"(x)); return r;
}
// exact for tf32-rounded normal-range values (10-bit mantissa fits fp16)
__device__ __forceinline__ uint32_t packh2(float lo, float hi) {
    __half2 h = __floats2half2_rn(lo, hi);
    return *reinterpret_cast<uint32_t*>(&h);
}
__device__ __forceinline__ uint32_t smem_u32(const void* p) {
    uint32_t a;
    asm("{ .reg .u64 t; cvta.to.shared.u64 t, %1; cvt.u32.u64 %0, t; }" : "=r"(a) : "l"(p));
    return a;
}
#define MBAR_INIT(a, n)  asm volatile("mbarrier.init.shared.b64 [%0], %1;" :: "r"(a), "r"((uint32_t)(n)) : "memory")
#define MBAR_EXPECT_TX(a, n) asm volatile("mbarrier.arrive.expect_tx.shared.b64 _, [%0], %1;" :: "r"(a), "r"((uint32_t)(n)) : "memory")
#define MBAR_WAIT(a, ph) do {                                                   \
    uint32_t _m = (a); uint32_t _p = (ph); uint32_t _d;                         \
    asm volatile("{\n\t.reg .pred p;\n\t"                                       \
        "mbarrier.try_wait.parity.acquire.cta.shared::cta.b64 p, [%1], %2;\n\t" \
        "selp.b32 %0, 1, 0, p;\n\t}" : "=r"(_d) : "r"(_m), "r"(_p) : "memory"); \
    if (!_d) {                                                                  \
        asm volatile("{\n\t.reg .pred P1;\n\t"                                  \
            "W%=:\n\t"                                                          \
            "mbarrier.try_wait.parity.acquire.cta.shared::cta.b64 P1, [%0], %1, 0x989680;\n\t" \
            "@P1 bra.uni D%=;\n\t"                                              \
            "bra.uni W%=;\n\t"                                                  \
            "D%=:\n\t}" :: "r"(_m), "r"(_p) : "memory");                        \
    } } while (0)
#define BULK_G2S(dst, src, bytes, mbar) \
    asm volatile("cp.async.bulk.shared::cluster.global.mbarrier::complete_tx::bytes [%0], [%1], %2, [%3];" \
        :: "r"(dst), "l"(src), "r"((uint32_t)(bytes)), "r"(mbar) : "memory")
#define REDADD(addr, v) \
    asm volatile("red.global.add.f32 [%0], %1;" :: "l"(addr), "f"(v) : "memory")

// fp16 m16n8k16, fp32 accum
__device__ __forceinline__ void mma16(float* d, uint32_t a0, uint32_t a1,
                                      uint32_t a2, uint32_t a3,
                                      uint32_t b0, uint32_t b1) {
    asm volatile(
        "mma.sync.aligned.m16n8k16.row.col.f32.f16.f16.f32 "
        "{%0,%1,%2,%3}, {%4,%5,%6,%7}, {%8,%9}, {%0,%1,%2,%3};"
        : "+f"(d[0]), "+f"(d[1]), "+f"(d[2]), "+f"(d[3])
        : "r"(a0), "r"(a1), "r"(a2), "r"(a3), "r"(b0), "r"(b1));
}

// -------- device scratch --------
__device__ float g_logits[N_PTS * E_EXP];
__device__ int   g_expert[N_PTS];
__device__ int   g_counts[E_EXP];
__device__ int   g_offsets[E_EXP + 1];
__device__ int   g_cursor[E_EXP];
__device__ int   g_perm[N_PTS];
// g1 activations fp16 A-frag layout: [band512][kt28][row128][c4] uint2  (58.7 MB)
__device__ __align__(16) uint2 g_g1p[(size_t)512 * GNCH * GASLAB_U2];
// gate W2 fp16 B-frag: [tile4][ch7][ksl4][c4][n116] uint2
__device__ __align__(16) uint2 g_W2t[4 * GNCH * GBSLAB_U2];
// siren weights fp16 B-frag: [e][l][ch3][ksl5][c4][n260] uint2
__device__ __align__(16) uint2 g_Bws[E_EXP * NLAYER * SNCH * SSLAB_U2];

// ---------------- init ----------------
__global__ void k_init() {
    int t = threadIdx.x;
    if (t < E_EXP) g_counts[t] = 0;
}

// ---------------- g1 precompute (fp16 A-frag layout) + zero logits ----------------
__global__ void __launch_bounds__(256) k_g1(
    const float* __restrict__ x, const float* __restrict__ W1, const float* __restrict__ b1)
{
    __shared__ float xs[GM * 3];
    int band = blockIdx.x;
    for (int i = threadIdx.x; i < GM * 3; i += 256) xs[i] = tf32q(x[band * GM * 3 + i]);
    for (int i = threadIdx.x; i < GM * E_EXP; i += 256) g_logits[band * GM * E_EXP + i] = 0.f;
    __syncthreads();
    uint2* dst = g_g1p + (size_t)band * (GNCH * GASLAB_U2);
    const int total = GNCH * GKC * GM * 4;   // 28 kt * 128 * 4 = 14336
    for (int s = threadIdx.x; s < total; s += 256) {
        int c4 = s & 3, row = (s >> 2) & 127, kt = s >> 9;
        int k0 = kt * 16 + 2 * c4;
        const float* xr = xs + row * 3;
        float g[4];
#pragma unroll
        for (int q = 0; q < 4; q++) {
            int k = k0 + (q & 1) + 8 * (q >> 1);
            float v = 0.f;
            if (k < M_DIM)
                v = tf32q(fmaxf(xr[0] * tf32q(W1[k]) + xr[1] * tf32q(W1[M_DIM + k])
                              + xr[2] * tf32q(W1[2 * M_DIM + k]) + b1[k], 0.f));
            g[q] = v;
        }
        uint2 v; v.x = packh2(g[0], g[1]); v.y = packh2(g[2], g[3]);
        dst[s] = v;
    }
}

// ---------------- weight preps ----------------
__global__ void k_prep_gateB(const float* __restrict__ W2) {
    const int total = 4 * GNCH * GBSLAB_U2;   // 51968
    for (int s = blockIdx.x * blockDim.x + threadIdx.x; s < total;
         s += gridDim.x * blockDim.x) {
        int n = s % GNPAD;
        int c4 = (s / GNPAD) & 3;
        int ksl = (s / (GNPAD * 4)) & 3;
        int ch = (s / GBSLAB_U2) % GNCH;
        int tile = s / (GBSLAB_U2 * GNCH);
        int k0 = (ch * GKC + ksl) * 16 + 2 * c4;
        int col = tile * GNT + n;
        float w[4] = {0.f, 0.f, 0.f, 0.f};
        if (n < GNT && col < M_DIM) {
#pragma unroll
            for (int q = 0; q < 4; q++) {
                int k = k0 + (q & 1) + 8 * (q >> 1);
                if (k < M_DIM) w[q] = tf32q(W2[(size_t)k * M_DIM + col]);
            }
        }
        uint2 v; v.x = packh2(w[0], w[1]); v.y = packh2(w[2], w[3]);
        g_W2t[s] = v;
    }
}
__global__ void k_prep_siren(const float* __restrict__ sWh,
                             const float* __restrict__ sWo,
                             const float* __restrict__ dW1)
{
    int el = blockIdx.x >> 3;             // 0..39
    int part = blockIdx.x & 7;
    int e = el / NLAYER, l = el % NLAYER;
    const float* W;
    if (l < 3)       W = sWh + ((size_t)(l * E_EXP + e)) * F_DIM * F_DIM;
    else if (l == 3) W = sWo + (size_t)e * F_DIM * F_DIM;
    else             W = dW1 + (size_t)e * F_DIM * F_DIM;
    uint2* dst = g_Bws + (size_t)el * (SNCH * SSLAB_U2);
    const int total = SNCH * SSLAB_U2;    // 15600
    for (int s = part * 256 + threadIdx.x; s < total; s += 2048) {
        int n = s % SNPAD;
        int c4 = (s / SNPAD) & 3;
        int ksl = (s / (SNPAD * 4)) % SKC;
        int ch = s / SSLAB_U2;
        int k0 = (ch * SKC + ksl) * 16 + 2 * c4;
        float w[4] = {0.f, 0.f, 0.f, 0.f};
        if (n < F_DIM) {
#pragma unroll
            for (int q = 0; q < 4; q++) {
                int k = k0 + (q & 1) + 8 * (q >> 1);
                if (k < F_DIM) w[q] = tf32q(W[k * F_DIM + n]);
            }
        }
        uint2 v; v.x = packh2(w[0], w[1]); v.y = packh2(w[2], w[3]);
        dst[s] = v;
    }
}

// ---------------- gating GEMM (fp16 mma) + fused partial logits ----------------
__global__ void __launch_bounds__(256, 2) k_gate(
    const float* __restrict__ b2, const float* __restrict__ W3)
{
    extern __shared__ float smf[];
    uint2* Af = (uint2*)smf;                 // 2 x GASLAB_U2
    uint2* Bf = Af + 2 * GASLAB_U2;          // 2 x GBSLAB_U2
    __shared__ __align__(8) unsigned long long mbar[2];
    const int tid = threadIdx.x;
    const int wid = tid >> 5, lane = tid & 31;
    const int r4 = lane >> 2, c4 = lane & 3;
    const int band = blockIdx.y;
    const int tile = blockIdx.x;
    const int wrow = (wid & 3) * 32;
    const int wcol = (wid >> 2) * 56;
    const uint32_t mb0 = smem_u32(&mbar[0]);

    const char* srcA = (const char*)(g_g1p + (size_t)band * GNCH * GASLAB_U2);
    const char* srcB = (const char*)(g_W2t + (size_t)tile * GNCH * GBSLAB_U2);

    float acc[2][7][4];
#pragma unroll
    for (int m = 0; m < 2; m++)
#pragma unroll
        for (int nb = 0; nb < 7; nb++)
#pragma unroll
            for (int j = 0; j < 4; j++) acc[m][nb][j] = 0.f;

    if (tid == 0) { MBAR_INIT(mb0, 1); MBAR_INIT(mb0 + 8, 1); }
    __syncthreads();
    if (tid == 0) {
        MBAR_EXPECT_TX(mb0, GBYTES);
        BULK_G2S(smem_u32(Af), srcA, GASLAB_U2 * 8, mb0);
        BULK_G2S(smem_u32(Bf), srcB, GBSLAB_U2 * 8, mb0);
    }

#pragma unroll 1
    for (int ch = 0; ch < GNCH; ch++) {
        const int s = ch & 1, ph = (ch >> 1) & 1;
        MBAR_WAIT(mb0 + 8 * s, ph);
        __syncthreads();
        if (ch + 1 < GNCH && tid == 0) {
            const int t = s ^ 1;
            MBAR_EXPECT_TX(mb0 + 8 * t, GBYTES);
            BULK_G2S(smem_u32(Af + t * GASLAB_U2), srcA + (size_t)(ch + 1) * GASLAB_U2 * 8, GASLAB_U2 * 8, mb0 + 8 * t);
            BULK_G2S(smem_u32(Bf + t * GBSLAB_U2), srcB + (size_t)(ch + 1) * GBSLAB_U2 * 8, GBSLAB_U2 * 8, mb0 + 8 * t);
        }
        const uint2* Ab = Af + s * GASLAB_U2;
        const uint2* Bb = Bf + s * GBSLAB_U2;
#pragma unroll
        for (int ks = 0; ks < GKC; ks++) {
            uint32_t a[2][4];
#pragma unroll
            for (int mb = 0; mb < 2; mb++) {
                int r = wrow + 16 * mb + r4;
                uint2 p = Ab[(ks * GM + r) * 4 + c4];
                uint2 q = Ab[(ks * GM + r + 8) * 4 + c4];
                a[mb][0] = p.x; a[mb][1] = q.x; a[mb][2] = p.y; a[mb][3] = q.y;
            }
#pragma unroll
            for (int nb = 0; nb < 7; nb++) {
                uint2 b = Bb[(ks * 4 + c4) * GNPAD + wcol + nb * 8 + r4];
                mma16(acc[0][nb], a[0][0], a[0][1], a[0][2], a[0][3], b.x, b.y);
                mma16(acc[1][nb], a[1][0], a[1][1], a[1][2], a[1][3], b.x, b.y);
            }
        }
    }

    // fused epilogue: g2 = tf32q(relu(acc+b2)); partial logits = g2 . W3
    float s[4][8];
#pragma unroll
    for (int ri = 0; ri < 4; ri++)
#pragma unroll
        for (int ee = 0; ee < 8; ee++) s[ri][ee] = 0.f;
#pragma unroll
    for (int mb = 0; mb < 2; mb++) {
#pragma unroll
        for (int nb = 0; nb < 7; nb++) {
#pragma unroll
            for (int h = 0; h < 2; h++) {
                int col = tile * GNT + wcol + nb * 8 + 2 * c4 + h;
                if (col < M_DIM) {
                    float4 wa = *(const float4*)(W3 + col * 8);
                    float4 wb = *(const float4*)(W3 + col * 8 + 4);
                    float bb = b2[col];
#pragma unroll
                    for (int hr = 0; hr < 2; hr++) {
                        int ri = mb * 2 + hr;
                        float g = tf32q(fmaxf(acc[mb][nb][2 * hr + h] + bb, 0.f));
                        s[ri][0] = fmaf(g, tf32q(wa.x), s[ri][0]);
                        s[ri][1] = fmaf(g, tf32q(wa.y), s[ri][1]);
                        s[ri][2] = fmaf(g, tf32q(wa.z), s[ri][2]);
                        s[ri][3] = fmaf(g, tf32q(wa.w), s[ri][3]);
                        s[ri][4] = fmaf(g, tf32q(wb.x), s[ri][4]);
                        s[ri][5] = fmaf(g, tf32q(wb.y), s[ri][5]);
                        s[ri][6] = fmaf(g, tf32q(wb.z), s[ri][6]);
                        s[ri][7] = fmaf(g, tf32q(wb.w), s[ri][7]);
                    }
                }
            }
        }
    }
#pragma unroll
    for (int ri = 0; ri < 4; ri++)
#pragma unroll
        for (int ee = 0; ee < 8; ee++) {
            float v = s[ri][ee];
            v += __shfl_xor_sync(0xffffffffu, v, 1);
            v += __shfl_xor_sync(0xffffffffu, v, 2);
            s[ri][ee] = v;
        }
    if (c4 == 0) {
#pragma unroll
        for (int ri = 0; ri < 4; ri++) {
            int row = band * GM + wrow + 16 * (ri >> 1) + r4 + 8 * (ri & 1);
            float* dst = g_logits + (size_t)row * 8;
#pragma unroll
            for (int ee = 0; ee < 8; ee++) REDADD(dst + ee, s[ri][ee]);
        }
    }
}

// ---------------- argmax over fused logits ----------------
__global__ void __launch_bounds__(256) k_argmax(const float* __restrict__ b3) {
    int n = blockIdx.x * blockDim.x + threadIdx.x;
    if (n >= N_PTS) return;
    const float* lg = g_logits + (size_t)n * 8;
    float best = lg[0] + b3[0]; int bi = 0;
#pragma unroll
    for (int e = 1; e < 8; e++) {
        float v = lg[e] + b3[e];
        if (v > best) { best = v; bi = e; }
    }
    g_expert[n] = bi;
    atomicAdd(&g_counts[bi], 1);
}

// ---------------- scan + KL (one-hot => constant) ----------------
__global__ void k_scan(float* out, int kl_idx) {
    if (threadIdx.x == 0) {
        int off = 0;
        for (int e = 0; e < E_EXP; e++) {
            g_offsets[e] = off;
            off += g_counts[e];
            g_cursor[e] = 0;
        }
        g_offsets[E_EXP] = off;
        out[kl_idx] = logf(0.125f) - 0.875f * logf(1e-10f);
    }
}

// ---------------- scatter ----------------
__global__ void k_scatter() {
    int n = blockIdx.x * blockDim.x + threadIdx.x;
    if (n >= N_PTS) return;
    int e = g_expert[n];
    int p = atomicAdd(&g_cursor[e], 1);
    g_perm[g_offsets[e] + p] = n;
}

// ---------------- fused SIREN + decoder (fp16 mma, in-place A, 3-stage B) ----------------
__global__ void __launch_bounds__(STHREADS, 1) k_siren(
    const float* __restrict__ x,
    const float* __restrict__ sW1, const float* __restrict__ sb1,
    const float* __restrict__ sbh, const float* __restrict__ sbo,
    const float* __restrict__ db1,
    const float* __restrict__ dW2, const float* __restrict__ db2,
    float* __restrict__ out)
{
    extern __shared__ float smf[];
    uint2* Af = (uint2*)smf;                 // SABUF_U2 (in-place)
    uint2* Bf = Af + SABUF_U2;               // 3 x SSLAB_U2
    uint32_t* Aw = (uint32_t*)smf;           // 32-bit view of A
    __shared__ float xs[TMS * 3];
    __shared__ float part[4][TMS][3];
    __shared__ __align__(8) unsigned long long mbar[3];

    const int e = blockIdx.y;
    const int tid = threadIdx.x;
    const int wid = tid >> 5, lane = tid & 31;
    const int r4 = lane >> 2, c4 = lane & 3;
    const int beg = g_offsets[e], end = g_offsets[e + 1];
    const int start = beg + blockIdx.x * TMS;
    if (start >= end) return;
    const int npts = min(TMS, end - start);
    const uint32_t mb0 = smem_u32(&mbar[0]);

    const int wrow = (wid & 3) * 32;
    const int ng = wid >> 2;                 // 0..3
    const int wcol = ng * 64;
    const char* bsrc = (const char*)(g_Bws + (size_t)e * (NLAYER * SNCH) * SSLAB_U2);

    if (tid == 0) { MBAR_INIT(mb0, 1); MBAR_INIT(mb0 + 8, 1); MBAR_INIT(mb0 + 16, 1); }
    if (tid < TMS) {
        float x0 = 0.f, x1 = 0.f, x2 = 0.f;
        if (tid < npts) {
            int n = g_perm[start + tid];
            x0 = tf32q(x[n * 3]); x1 = tf32q(x[n * 3 + 1]); x2 = tf32q(x[n * 3 + 2]);
        }
        xs[tid * 3] = x0; xs[tid * 3 + 1] = x1; xs[tid * 3 + 2] = x2;
    }
    __syncthreads();
    if (tid == 0) {
        MBAR_EXPECT_TX(mb0, SBYTES);
        BULK_G2S(smem_u32(Bf), bsrc, SBYTES, mb0);
        MBAR_EXPECT_TX(mb0 + 8, SBYTES);
        BULK_G2S(smem_u32(Bf + SSLAB_U2), bsrc + SBYTES, SBYTES, mb0 + 8);
    }

    // first sine layer -> A buffer (fp16 A-frag layout, half2 per store)
    {
        const float* W1e = sW1 + (size_t)e * 3 * F_DIM;
        const float* b1e = sb1 + (size_t)e * F_DIM;
        for (int idx = tid; idx < TMS * 120; idx += STHREADS) {
            int row = idx / 120, p = idx - row * 120;
            int col0 = 2 * p;
            float v0 = 0.f, v1 = 0.f;
            float xa = xs[row * 3], xb = xs[row * 3 + 1], xc = xs[row * 3 + 2];
            if (col0 < F_DIM)
                v0 = tf32q(sinf(30.0f * (xa * tf32q(W1e[col0]) + xb * tf32q(W1e[F_DIM + col0])
                     + xc * tf32q(W1e[2 * F_DIM + col0]) + b1e[col0])));
            if (col0 + 1 < F_DIM)
                v1 = tf32q(sinf(30.0f * (xa * tf32q(W1e[col0 + 1]) + xb * tf32q(W1e[F_DIM + col0 + 1])
                     + xc * tf32q(W1e[2 * F_DIM + col0 + 1]) + b1e[col0 + 1])));
            int kt = col0 >> 4, within = col0 & 15;
            int h = within >> 3, c4p = (within & 7) >> 1;
            Aw[((kt * TMS + row) * 4 + c4p) * 2 + h] = packh2(v0, v1);
        }
    }
    __syncthreads();

    int ci = 0;
#pragma unroll 1
    for (int l = 0; l < NLAYER; l++) {
        float acc[2][8][4];
#pragma unroll
        for (int m = 0; m < 2; m++)
#pragma unroll
            for (int nb = 0; nb < 8; nb++)
#pragma unroll
                for (int j = 0; j < 4; j++) acc[m][nb][j] = 0.f;

#pragma unroll 1
        for (int chn = 0; chn < SNCH; chn++, ci++) {
            const int st = ci % 3, ph = (ci / 3) & 1;
            MBAR_WAIT(mb0 + 8 * st, ph);
            __syncthreads();
            if (ci + 2 < NCI && tid == 0) {
                const int t = (ci + 2) % 3;
                MBAR_EXPECT_TX(mb0 + 8 * t, SBYTES);
                BULK_G2S(smem_u32(Bf + t * SSLAB_U2), bsrc + (size_t)(ci + 2) * SBYTES, SBYTES, mb0 + 8 * t);
            }
            const uint2* Bb = Bf + st * SSLAB_U2;
#pragma unroll
            for (int ksl = 0; ksl < SKC; ksl++) {
                int kg = chn * SKC + ksl;
                uint32_t a[2][4];
#pragma unroll
                for (int mb = 0; mb < 2; mb++) {
                    int r = wrow + 16 * mb + r4;
                    uint2 p = Af[(kg * TMS + r) * 4 + c4];
                    uint2 q = Af[(kg * TMS + r + 8) * 4 + c4];
                    a[mb][0] = p.x; a[mb][1] = q.x; a[mb][2] = p.y; a[mb][3] = q.y;
                }
#pragma unroll
                for (int nb = 0; nb < 8; nb++) {
                    uint2 b = Bb[(ksl * 4 + c4) * SNPAD + wcol + nb * 8 + r4];
                    mma16(acc[0][nb], a[0][0], a[0][1], a[0][2], a[0][3], b.x, b.y);
                    mma16(acc[1][nb], a[1][0], a[1][1], a[1][2], a[1][3], b.x, b.y);
                }
            }
        }

        if (l < 4) {
            // all MMA reads of A must drain before in-place overwrite
            __syncthreads();
            const float* bias = (l < 3) ? (sbh + (size_t)(l * E_EXP + e) * F_DIM)
                                        : (sbo + (size_t)e * F_DIM);
#pragma unroll
            for (int mb = 0; mb < 2; mb++) {
                int r = wrow + 16 * mb + r4;
#pragma unroll
                for (int nb = 0; nb < 8; nb++) {
                    int j0 = wcol + nb * 8 + 2 * c4;
                    if (j0 >= 240) continue;
                    int kt = j0 >> 4, within = j0 & 15;
                    int h = within >> 3, c4p = (within & 7) >> 1;
#pragma unroll
                    for (int hr = 0; hr < 2; hr++) {
                        int row = r + 8 * hr;
                        float v0 = 0.f, v1 = 0.f;
                        if (j0 < F_DIM) {
                            v0 = acc[mb][nb][2 * hr] + bias[j0];
                            if (l < 3) v0 = sinf(30.0f * v0);
                            v0 = tf32q(v0);
                        }
                        if (j0 + 1 < F_DIM) {
                            v1 = acc[mb][nb][2 * hr + 1] + bias[j0 + 1];
                            if (l < 3) v1 = sinf(30.0f * v1);
                            v1 = tf32q(v1);
                        }
                        Aw[((kt * TMS + row) * 4 + c4p) * 2 + h] = packh2(v0, v1);
                    }
                }
            }
        } else {
            // dec1 (relu) + dec2 (236->3) fused from registers
            float s[4][3];
#pragma unroll
            for (int ri = 0; ri < 4; ri++)
#pragma unroll
                for (int o = 0; o < 3; o++) s[ri][o] = 0.f;
#pragma unroll
            for (int mb = 0; mb < 2; mb++) {
#pragma unroll
                for (int nb = 0; nb < 8; nb++) {
                    int j0 = wcol + nb * 8 + 2 * c4;
                    if (j0 >= F_DIM) continue;
#pragma unroll
                    for (int hr = 0; hr < 2; hr++) {
                        int ri = mb * 2 + hr;
                        float a0 = tf32q(fmaxf(acc[mb][nb][2 * hr] + db1[j0], 0.f));
                        s[ri][0] = fmaf(a0, tf32q(dW2[j0 * 3 + 0]), s[ri][0]);
                        s[ri][1] = fmaf(a0, tf32q(dW2[j0 * 3 + 1]), s[ri][1]);
                        s[ri][2] = fmaf(a0, tf32q(dW2[j0 * 3 + 2]), s[ri][2]);
                        if (j0 + 1 < F_DIM) {
                            float a1 = tf32q(fmaxf(acc[mb][nb][2 * hr + 1] + db1[j0 + 1], 0.f));
                            s[ri][0] = fmaf(a1, tf32q(dW2[(j0 + 1) * 3 + 0]), s[ri][0]);
                            s[ri][1] = fmaf(a1, tf32q(dW2[(j0 + 1) * 3 + 1]), s[ri][1]);
                            s[ri][2] = fmaf(a1, tf32q(dW2[(j0 + 1) * 3 + 2]), s[ri][2]);
                        }
                    }
                }
            }
#pragma unroll
            for (int ri = 0; ri < 4; ri++)
#pragma unroll
                for (int o = 0; o < 3; o++) {
                    float v = s[ri][o];
                    v += __shfl_xor_sync(0xffffffffu, v, 1);
                    v += __shfl_xor_sync(0xffffffffu, v, 2);
                    s[ri][o] = v;
                }
            if (c4 == 0) {
#pragma unroll
                for (int ri = 0; ri < 4; ri++) {
                    int row = wrow + 16 * (ri >> 1) + r4 + 8 * (ri & 1);
#pragma unroll
                    for (int o = 0; o < 3; o++) part[ng][row][o] = s[ri][o];
                }
            }
            __syncthreads();
            for (int idx = tid; idx < TMS * 3; idx += STHREADS) {
                int p = idx / 3, o = idx - p * 3;
                if (p < npts) {
                    float v = db2[o] + part[0][p][o] + part[1][p][o]
                            + part[2][p][o] + part[3][p][o];
                    out[g_perm[start + p] * 3 + o] = v;
                }
            }
        }
    }
}

// ---------------- launch ----------------
extern "C" void kernel_launch(void* const* d_in, const int* in_sizes, int n_in,
                              void* d_out, int out_size)
{
    const float* x   = (const float*)d_in[0];
    const float* sW1 = (const float*)d_in[1];
    const float* sb1 = (const float*)d_in[2];
    const float* sWh = (const float*)d_in[3];
    const float* sbh = (const float*)d_in[4];
    const float* sWo = (const float*)d_in[5];
    const float* sbo = (const float*)d_in[6];
    const float* mW1 = (const float*)d_in[7];
    const float* mb1 = (const float*)d_in[8];
    const float* mW2 = (const float*)d_in[9];
    const float* mb2 = (const float*)d_in[10];
    const float* mW3 = (const float*)d_in[11];
    const float* mb3 = (const float*)d_in[12];
    const float* dW1 = (const float*)d_in[13];
    const float* db1 = (const float*)d_in[14];
    const float* dW2 = (const float*)d_in[15];
    const float* db2 = (const float*)d_in[16];
    float* out = (float*)d_out;

    size_t smem_gate  = (size_t)(2 * GASLAB_U2 + 2 * GBSLAB_U2) * 8;  // 62464 B
    size_t smem_siren = (size_t)(SABUF_U2 + 3 * SSLAB_U2) * 8;        // 186240 B
    cudaFuncSetAttribute(k_gate,  cudaFuncAttributeMaxDynamicSharedMemorySize, (int)smem_gate);
    cudaFuncSetAttribute(k_siren, cudaFuncAttributeMaxDynamicSharedMemorySize, (int)smem_siren);

    k_init<<<1, 32>>>();
    k_g1<<<512, 256>>>(x, mW1, mb1);
    k_prep_gateB<<<256, 256>>>(mW2);
    k_prep_siren<<<E_EXP * NLAYER * 8, 256>>>(sWh, sWo, dW1);

    dim3 gG(4, 512);                         // (N tiles, bands)
    k_gate<<<gG, 256, smem_gate>>>(mb2, mW3);

    k_argmax<<<N_PTS / 256, 256>>>(mb3);

    k_scan<<<1, 32>>>(out, out_size - 1);

    k_scatter<<<N_PTS / 256, 256>>>();

    dim3 gS((N_PTS + TMS - 1) / TMS, E_EXP); // (512, 8), extras exit
    k_siren<<<gS, STHREADS, smem_siren>>>(x, sW1, sb1, sbh, sbo, db1, dW2, db2, out);
}